// round 1
// baseline (speedup 1.0000x reference)
#include <cuda_runtime.h>
#include <math.h>

// Problem constants
#define BB 4
#define SEQ 2048
#define DIM 2048
#define NH 16
#define HD 128
#define NTOK (BB * SEQ)        // 8192
#define QKVC (3 * DIM)         // 6144

// Scratch (device globals: allocation-free)
__device__ float g_qkv[(size_t)NTOK * QKVC];   // 192 MB
__device__ float g_ctx[(size_t)NTOK * DIM];    // 64 MB
__device__ float g_cos[SEQ * (HD / 2)];
__device__ float g_sin[SEQ * (HD / 2)];

// ---------------------------------------------------------------------------
// RoPE tables in double precision (angle accuracy matters through softmax)
// ---------------------------------------------------------------------------
__global__ void build_rope_tables() {
    int idx = blockIdx.x * blockDim.x + threadIdx.x;
    if (idx >= SEQ * (HD / 2)) return;
    int pos = idx / (HD / 2);
    int i = idx % (HD / 2);
    double inv = exp(-((double)(2 * i) / (double)HD) * log(10000.0));
    double ang = (double)pos * inv;
    g_cos[idx] = (float)cos(ang);
    g_sin[idx] = (float)sin(ang);
}

// ---------------------------------------------------------------------------
// Apply RoPE in-place to q and k slices of g_qkv
// layout per token: [q(16*128) | k(16*128) | v(16*128)]
// ---------------------------------------------------------------------------
__global__ void rope_kernel() {
    int idx = blockIdx.x * blockDim.x + threadIdx.x;
    const int total = NTOK * 2 * NH * (HD / 2);   // 16,777,216
    if (idx >= total) return;
    int i  = idx & 63;            // pair index 0..63
    int h  = (idx >> 6) & 15;     // head
    int qk = (idx >> 10) & 1;     // 0=q, 1=k
    int t  = idx >> 11;           // token 0..8191
    int pos = t & (SEQ - 1);
    float c = g_cos[pos * (HD / 2) + i];
    float s = g_sin[pos * (HD / 2) + i];
    float* p = g_qkv + (size_t)t * QKVC + qk * DIM + h * HD + 2 * i;
    float x0 = p[0], x1 = p[1];
    p[0] = x0 * c - x1 * s;
    p[1] = x1 * c + x0 * s;
}

// ---------------------------------------------------------------------------
// SGEMM: C[M,N] = A[M,K] @ B[K,N] + bias[N]
// 128x128x8 tile, 256 threads, 8x8 per thread. M,N,K multiples of 128/8.
// ---------------------------------------------------------------------------
__global__ __launch_bounds__(256)
void sgemm_bias(const float* __restrict__ A, const float* __restrict__ B,
                const float* __restrict__ bias, float* __restrict__ C,
                int M, int N, int K) {
    __shared__ float As[8][128];
    __shared__ float Bs[8][128];
    int tid = threadIdx.x;
    int brow = blockIdx.y * 128;
    int bcol = blockIdx.x * 128;
    int trow = (tid >> 4) * 8;
    int tcol = (tid & 15) * 8;

    float acc[8][8];
#pragma unroll
    for (int i = 0; i < 8; i++)
#pragma unroll
        for (int j = 0; j < 8; j++) acc[i][j] = 0.f;

    int arow = tid >> 1;
    int acol = (tid & 1) * 4;
    int brw = tid >> 5;
    int bcl = (tid & 31) * 4;
    const float* Ap = A + (size_t)(brow + arow) * K + acol;
    const float* Bp = B + (size_t)brw * N + bcol + bcl;

    for (int k0 = 0; k0 < K; k0 += 8) {
        float4 av = *(const float4*)(Ap + k0);
        float4 bv = *(const float4*)(Bp + (size_t)k0 * N);
        __syncthreads();
        As[acol + 0][arow] = av.x;
        As[acol + 1][arow] = av.y;
        As[acol + 2][arow] = av.z;
        As[acol + 3][arow] = av.w;
        *(float4*)&Bs[brw][bcl] = bv;
        __syncthreads();
#pragma unroll
        for (int kk = 0; kk < 8; ++kk) {
            float a[8], b[8];
            *(float4*)&a[0] = *(const float4*)&As[kk][trow];
            *(float4*)&a[4] = *(const float4*)&As[kk][trow + 4];
            *(float4*)&b[0] = *(const float4*)&Bs[kk][tcol];
            *(float4*)&b[4] = *(const float4*)&Bs[kk][tcol + 4];
#pragma unroll
            for (int i = 0; i < 8; i++)
#pragma unroll
                for (int j = 0; j < 8; j++)
                    acc[i][j] += a[i] * b[j];
        }
    }

    float bj[8];
#pragma unroll
    for (int j = 0; j < 8; j++) bj[j] = bias[bcol + tcol + j];
#pragma unroll
    for (int i = 0; i < 8; i++) {
        float* Cp = C + (size_t)(brow + trow + i) * N + bcol + tcol;
        float4 o0 = make_float4(acc[i][0] + bj[0], acc[i][1] + bj[1],
                                acc[i][2] + bj[2], acc[i][3] + bj[3]);
        float4 o1 = make_float4(acc[i][4] + bj[4], acc[i][5] + bj[5],
                                acc[i][6] + bj[6], acc[i][7] + bj[7]);
        *(float4*)Cp = o0;
        *(float4*)(Cp + 4) = o1;
    }
}

// ---------------------------------------------------------------------------
// Flash attention (fp32, causal). Q tile 64, K tile 64, 256 threads.
// Dynamic smem layout (floats):
//   Qst [HD][65]  transposed Q tile
//   Kst [HD][65]  transposed K tile
//   Vs  [64][HD]
//   Ss  [64][65]
//   m, l, corr [64] each
// ---------------------------------------------------------------------------
#define QT 64
#define KTLE 64
#define TP 65
#define KTP 65
#define SMEM_FLOATS (HD * TP + HD * TP + KTLE * HD + QT * KTP + 3 * QT)

__device__ __forceinline__ void load_tile_transposed(float* dst, const float* gsrc,
                                                     int tid) {
#pragma unroll
    for (int v = 0; v < 8; ++v) {
        int li = v * 256 + tid;
        int j = li >> 5;             // tile row 0..63
        int k4 = (li & 31) << 2;     // dim 0..124
        float4 x = *(const float4*)(gsrc + (size_t)j * QKVC + k4);
        dst[(k4 + 0) * TP + j] = x.x;
        dst[(k4 + 1) * TP + j] = x.y;
        dst[(k4 + 2) * TP + j] = x.z;
        dst[(k4 + 3) * TP + j] = x.w;
    }
}

__device__ __forceinline__ void load_tile_direct(float* dst, const float* gsrc,
                                                 int tid) {
#pragma unroll
    for (int v = 0; v < 8; ++v) {
        int li = v * 256 + tid;
        int j = li >> 5;
        int k4 = (li & 31) << 2;
        *(float4*)(dst + j * HD + k4) = *(const float4*)(gsrc + (size_t)j * QKVC + k4);
    }
}

__global__ __launch_bounds__(256)
void flash_attn(const float* __restrict__ qkv, float* __restrict__ ctx) {
    int qtile = blockIdx.x;
    int head = blockIdx.y;
    int batch = blockIdx.z;
    int q0 = qtile * QT;
    int tid = threadIdx.x;

    extern __shared__ float smem[];
    float* Qst = smem;
    float* Kst = Qst + HD * TP;
    float* Vs = Kst + HD * TP;
    float* Ss = Vs + KTLE * HD;
    float* m_s = Ss + QT * KTP;
    float* l_s = m_s + QT;
    float* cr_s = l_s + QT;

    const float scale = 0.08838834764831845f;  // 1/sqrt(128)

    const float* qbase = qkv + ((size_t)(batch * SEQ + q0)) * QKVC + head * HD;
    load_tile_transposed(Qst, qbase, tid);
    if (tid < QT) { m_s[tid] = -INFINITY; l_s[tid] = 0.f; }

    float acc[32];
#pragma unroll
    for (int d = 0; d < 32; ++d) acc[d] = 0.f;

    int orow = tid & 63;
    int od0 = (tid >> 6) * 32;
    int srow0 = (tid >> 4) * 4;
    int scol0 = (tid & 15) * 4;

    for (int kt = 0; kt <= qtile; ++kt) {
        int k0 = kt * KTLE;
        const float* kbase = qkv + ((size_t)(batch * SEQ + k0)) * QKVC + DIM + head * HD;
        const float* vbase = kbase + DIM;

        __syncthreads();
        load_tile_transposed(Kst, kbase, tid);
        load_tile_direct(Vs, vbase, tid);
        __syncthreads();

        // S = Q @ K^T  (4x4 per thread)
        float sacc[4][4];
#pragma unroll
        for (int i = 0; i < 4; i++)
#pragma unroll
            for (int j = 0; j < 4; j++) sacc[i][j] = 0.f;

#pragma unroll 4
        for (int k = 0; k < HD; ++k) {
            float qv[4], kv[4];
#pragma unroll
            for (int i = 0; i < 4; i++) qv[i] = Qst[k * TP + srow0 + i];
#pragma unroll
            for (int j = 0; j < 4; j++) kv[j] = Kst[k * TP + scol0 + j];
#pragma unroll
            for (int i = 0; i < 4; i++)
#pragma unroll
                for (int j = 0; j < 4; j++)
                    sacc[i][j] += qv[i] * kv[j];
        }

        // masked, scaled write to Ss
#pragma unroll
        for (int i = 0; i < 4; i++) {
            int gi = q0 + srow0 + i;
#pragma unroll
            for (int j = 0; j < 4; j++) {
                int gj = k0 + scol0 + j;
                float v = sacc[i][j] * scale;
                Ss[(srow0 + i) * KTP + scol0 + j] = (gj > gi) ? -INFINITY : v;
            }
        }
        __syncthreads();

        // online softmax: one thread per row
        if (tid < QT) {
            float mold = m_s[tid];
            float* srow = Ss + tid * KTP;
            float tm = -INFINITY;
            for (int j = 0; j < KTLE; ++j) tm = fmaxf(tm, srow[j]);
            float nm = fmaxf(mold, tm);
            float corr = __expf(mold - nm);
            float sum = 0.f;
            for (int j = 0; j < KTLE; ++j) {
                float p = __expf(srow[j] - nm);
                srow[j] = p;
                sum += p;
            }
            m_s[tid] = nm;
            l_s[tid] = l_s[tid] * corr + sum;
            cr_s[tid] = corr;
        }
        __syncthreads();

        // O = O*corr + P @ V  (thread owns row orow, dims [od0, od0+32))
        float corr = cr_s[orow];
#pragma unroll
        for (int d = 0; d < 32; ++d) acc[d] *= corr;
        const float* prow = Ss + orow * KTP;
        for (int j = 0; j < KTLE; ++j) {
            float p = prow[j];
            const float* vp = Vs + j * HD + od0;
#pragma unroll
            for (int d = 0; d < 32; d += 4) {
                float4 v4 = *(const float4*)(vp + d);
                acc[d + 0] += p * v4.x;
                acc[d + 1] += p * v4.y;
                acc[d + 2] += p * v4.z;
                acc[d + 3] += p * v4.w;
            }
        }
    }

    float invl = 1.0f / l_s[orow];
    float* op = ctx + ((size_t)(batch * SEQ + q0 + orow)) * DIM + head * HD + od0;
#pragma unroll
    for (int d = 0; d < 32; d += 4) {
        float4 o = make_float4(acc[d] * invl, acc[d + 1] * invl,
                               acc[d + 2] * invl, acc[d + 3] * invl);
        *(float4*)(op + d) = o;
    }
}

// ---------------------------------------------------------------------------
// Launch
// ---------------------------------------------------------------------------
extern "C" void kernel_launch(void* const* d_in, const int* in_sizes, int n_in,
                              void* d_out, int out_size) {
    const float* x      = (const float*)d_in[0];
    // d_in[1] = attn_mask (bool, causal) - implicit in kernel
    const float* Wqkv_w = (const float*)d_in[2];
    const float* Wqkv_b = (const float*)d_in[3];
    const float* Wout_w = (const float*)d_in[4];
    const float* Wout_b = (const float*)d_in[5];
    float* out = (float*)d_out;

    void* qkv_p = nullptr;
    void* ctx_p = nullptr;
    cudaGetSymbolAddress(&qkv_p, g_qkv);
    cudaGetSymbolAddress(&ctx_p, g_ctx);
    float* qkv = (float*)qkv_p;
    float* ctx = (float*)ctx_p;

    // 1) RoPE tables
    build_rope_tables<<<(SEQ * (HD / 2) + 255) / 256, 256>>>();

    // 2) QKV projection: [8192,6144] = x[8192,2048] @ Wqkv[2048,6144] + b
    sgemm_bias<<<dim3(QKVC / 128, NTOK / 128), 256>>>(x, Wqkv_w, Wqkv_b, qkv,
                                                      NTOK, QKVC, DIM);

    // 3) RoPE on q,k in place
    rope_kernel<<<(NTOK * 2 * NH * (HD / 2)) / 256, 256>>>();

    // 4) Flash attention
    static const size_t smem_bytes = (size_t)SMEM_FLOATS * sizeof(float);
    cudaFuncSetAttribute(flash_attn, cudaFuncAttributeMaxDynamicSharedMemorySize,
                         (int)smem_bytes);
    flash_attn<<<dim3(SEQ / QT, NH, BB), 256, smem_bytes>>>(qkv, ctx);

    // 5) Output projection: out[8192,2048] = ctx @ Wout + b
    sgemm_bias<<<dim3(DIM / 128, NTOK / 128), 256>>>(ctx, Wout_w, Wout_b, out,
                                                     NTOK, DIM, DIM);
}

// round 2
// speedup vs baseline: 1.9022x; 1.9022x over previous
#include <cuda_runtime.h>
#include <math.h>
#include <stdint.h>

// Problem constants
#define BB 4
#define SEQ 2048
#define DIM 2048
#define NH 16
#define HD 128
#define NTOK (BB * SEQ)        // 8192
#define QKVC (3 * DIM)         // 6144

// Scratch (device globals: allocation-free)
__device__ float g_qkv[(size_t)NTOK * QKVC];   // 192 MB
__device__ float g_ctx[(size_t)NTOK * DIM];    // 64 MB
__device__ float g_cos[SEQ * (HD / 2)];
__device__ float g_sin[SEQ * (HD / 2)];

// ---------------------------------------------------------------------------
// RoPE tables in double precision
// ---------------------------------------------------------------------------
__global__ void build_rope_tables() {
    int idx = blockIdx.x * blockDim.x + threadIdx.x;
    if (idx >= SEQ * (HD / 2)) return;
    int pos = idx / (HD / 2);
    int i = idx % (HD / 2);
    double inv = exp(-((double)(2 * i) / (double)HD) * log(10000.0));
    double ang = (double)pos * inv;
    g_cos[idx] = (float)cos(ang);
    g_sin[idx] = (float)sin(ang);
}

__global__ void rope_kernel() {
    int idx = blockIdx.x * blockDim.x + threadIdx.x;
    const int total = NTOK * 2 * NH * (HD / 2);
    if (idx >= total) return;
    int i  = idx & 63;
    int h  = (idx >> 6) & 15;
    int qk = (idx >> 10) & 1;
    int t  = idx >> 11;
    int pos = t & (SEQ - 1);
    float c = g_cos[pos * (HD / 2) + i];
    float s = g_sin[pos * (HD / 2) + i];
    float* p = g_qkv + (size_t)t * QKVC + qk * DIM + h * HD + 2 * i;
    float x0 = p[0], x1 = p[1];
    p[0] = x0 * c - x1 * s;
    p[1] = x1 * c + x0 * s;
}

// ---------------------------------------------------------------------------
// TF32 tensor-core GEMM: C[M,N] = A[M,K] @ B[K,N] + bias
// 128x128x32 tile, 256 threads (8 warps, 4x2), cp.async double buffering.
// Conflict-free fragment LDS: A stride 36 (bank=4g+t), B stride 136 (bank=8t+g).
// ---------------------------------------------------------------------------
#define BM 128
#define BN 128
#define BK 32
#define ASTRIDE 36            // BK + 4
#define BSTRIDE 136           // BN + 8
#define A_STAGE (BM * ASTRIDE)   // 4608 floats
#define B_STAGE (BK * BSTRIDE)   // 4352 floats
#define STAGE_FLOATS (A_STAGE + B_STAGE)  // 8960
#define GEMM_SMEM_BYTES (2 * STAGE_FLOATS * 4)  // 71680

__device__ __forceinline__ void cp_async16(float* smem, const float* gmem) {
    uint32_t s = (uint32_t)__cvta_generic_to_shared(smem);
    asm volatile("cp.async.cg.shared.global [%0], [%1], 16;\n" :: "r"(s), "l"(gmem));
}
__device__ __forceinline__ void cp_commit() {
    asm volatile("cp.async.commit_group;\n");
}
__device__ __forceinline__ void cp_wait_all() {
    asm volatile("cp.async.wait_group 0;\n");
}
__device__ __forceinline__ uint32_t f2tf32(float f) {
    uint32_t u;
    asm("cvt.rna.tf32.f32 %0, %1;\n" : "=r"(u) : "f"(f));
    return u;
}
__device__ __forceinline__ void mma_tf32(float* c, const uint32_t* a, const uint32_t* b) {
    asm volatile(
        "mma.sync.aligned.m16n8k8.row.col.f32.tf32.tf32.f32 "
        "{%0,%1,%2,%3}, {%4,%5,%6,%7}, {%8,%9}, {%0,%1,%2,%3};\n"
        : "+f"(c[0]), "+f"(c[1]), "+f"(c[2]), "+f"(c[3])
        : "r"(a[0]), "r"(a[1]), "r"(a[2]), "r"(a[3]), "r"(b[0]), "r"(b[1]));
}

__device__ __forceinline__ void load_a_stage(float* As, const float* A, int K,
                                             int brow, int ktile, int tid) {
#pragma unroll
    for (int v = 0; v < 4; v++) {
        int idx = v * 256 + tid;
        int row = idx >> 3;
        int ch = idx & 7;
        cp_async16(As + row * ASTRIDE + ch * 4,
                   A + (size_t)(brow + row) * K + ktile * BK + ch * 4);
    }
}
__device__ __forceinline__ void load_b_stage(float* Bs, const float* B, int N,
                                             int bcol, int ktile, int tid) {
#pragma unroll
    for (int v = 0; v < 4; v++) {
        int idx = v * 256 + tid;
        int row = idx >> 5;
        int ch = idx & 31;
        cp_async16(Bs + row * BSTRIDE + ch * 4,
                   B + (size_t)(ktile * BK + row) * N + bcol + ch * 4);
    }
}

__global__ __launch_bounds__(256, 2)
void gemm_tf32(const float* __restrict__ A, const float* __restrict__ B,
               const float* __restrict__ bias, float* __restrict__ C,
               int M, int N, int K) {
    extern __shared__ float sm[];
    int tid = threadIdx.x;
    int brow = blockIdx.y * BM;
    int bcol = blockIdx.x * BN;
    int warp = tid >> 5, lane = tid & 31;
    int wm = warp >> 1, wn = warp & 1;
    int g = lane >> 2, t = lane & 3;

    float c[2][8][4];
#pragma unroll
    for (int i = 0; i < 2; i++)
#pragma unroll
        for (int j = 0; j < 8; j++)
#pragma unroll
            for (int r = 0; r < 4; r++) c[i][j][r] = 0.f;

    const int NK = K / BK;

    load_a_stage(sm, A, K, brow, 0, tid);
    load_b_stage(sm + A_STAGE, B, N, bcol, 0, tid);
    cp_commit();

    int buf = 0;
    for (int kt = 0; kt < NK; kt++) {
        cp_wait_all();
        __syncthreads();
        if (kt + 1 < NK) {
            float* s2 = sm + (buf ^ 1) * STAGE_FLOATS;
            load_a_stage(s2, A, K, brow, kt + 1, tid);
            load_b_stage(s2 + A_STAGE, B, N, bcol, kt + 1, tid);
            cp_commit();
        }
        const float* As = sm + buf * STAGE_FLOATS;
        const float* Bs = As + A_STAGE;

#pragma unroll
        for (int ks = 0; ks < 4; ks++) {
            int k0 = ks * 8;
            uint32_t a[2][4], b[8][2];
#pragma unroll
            for (int mt = 0; mt < 2; mt++) {
                const float* ap = As + (wm * 32 + mt * 16 + g) * ASTRIDE + k0 + t;
                a[mt][0] = f2tf32(ap[0]);
                a[mt][1] = f2tf32(ap[8 * ASTRIDE]);
                a[mt][2] = f2tf32(ap[4]);
                a[mt][3] = f2tf32(ap[8 * ASTRIDE + 4]);
            }
#pragma unroll
            for (int nt = 0; nt < 8; nt++) {
                const float* bp = Bs + (k0 + t) * BSTRIDE + wn * 64 + nt * 8 + g;
                b[nt][0] = f2tf32(bp[0]);
                b[nt][1] = f2tf32(bp[4 * BSTRIDE]);
            }
#pragma unroll
            for (int mt = 0; mt < 2; mt++)
#pragma unroll
                for (int nt = 0; nt < 8; nt++)
                    mma_tf32(c[mt][nt], a[mt], b[nt]);
        }
        buf ^= 1;
    }

    // Epilogue: add bias, write fp32
#pragma unroll
    for (int mt = 0; mt < 2; mt++) {
        int r0 = brow + wm * 32 + mt * 16 + g;
#pragma unroll
        for (int nt = 0; nt < 8; nt++) {
            int col = bcol + wn * 64 + nt * 8 + 2 * t;
            float b0 = bias[col], b1 = bias[col + 1];
            float2 v0 = make_float2(c[mt][nt][0] + b0, c[mt][nt][1] + b1);
            float2 v1 = make_float2(c[mt][nt][2] + b0, c[mt][nt][3] + b1);
            *(float2*)(C + (size_t)r0 * N + col) = v0;
            *(float2*)(C + (size_t)(r0 + 8) * N + col) = v1;
        }
    }
}

// ---------------------------------------------------------------------------
// Flash attention (fp32, causal) — unchanged from R1
// ---------------------------------------------------------------------------
#define QT 64
#define KTLE 64
#define TP 65
#define KTP 65
#define SMEM_FLOATS (HD * TP + HD * TP + KTLE * HD + QT * KTP + 3 * QT)

__device__ __forceinline__ void load_tile_transposed(float* dst, const float* gsrc,
                                                     int tid) {
#pragma unroll
    for (int v = 0; v < 8; ++v) {
        int li = v * 256 + tid;
        int j = li >> 5;
        int k4 = (li & 31) << 2;
        float4 x = *(const float4*)(gsrc + (size_t)j * QKVC + k4);
        dst[(k4 + 0) * TP + j] = x.x;
        dst[(k4 + 1) * TP + j] = x.y;
        dst[(k4 + 2) * TP + j] = x.z;
        dst[(k4 + 3) * TP + j] = x.w;
    }
}

__device__ __forceinline__ void load_tile_direct(float* dst, const float* gsrc,
                                                 int tid) {
#pragma unroll
    for (int v = 0; v < 8; ++v) {
        int li = v * 256 + tid;
        int j = li >> 5;
        int k4 = (li & 31) << 2;
        *(float4*)(dst + j * HD + k4) = *(const float4*)(gsrc + (size_t)j * QKVC + k4);
    }
}

__global__ __launch_bounds__(256)
void flash_attn(const float* __restrict__ qkv, float* __restrict__ ctx) {
    int qtile = blockIdx.x;
    int head = blockIdx.y;
    int batch = blockIdx.z;
    int q0 = qtile * QT;
    int tid = threadIdx.x;

    extern __shared__ float smem[];
    float* Qst = smem;
    float* Kst = Qst + HD * TP;
    float* Vs = Kst + HD * TP;
    float* Ss = Vs + KTLE * HD;
    float* m_s = Ss + QT * KTP;
    float* l_s = m_s + QT;
    float* cr_s = l_s + QT;

    const float scale = 0.08838834764831845f;

    const float* qbase = qkv + ((size_t)(batch * SEQ + q0)) * QKVC + head * HD;
    load_tile_transposed(Qst, qbase, tid);
    if (tid < QT) { m_s[tid] = -INFINITY; l_s[tid] = 0.f; }

    float acc[32];
#pragma unroll
    for (int d = 0; d < 32; ++d) acc[d] = 0.f;

    int orow = tid & 63;
    int od0 = (tid >> 6) * 32;
    int srow0 = (tid >> 4) * 4;
    int scol0 = (tid & 15) * 4;

    for (int kt = 0; kt <= qtile; ++kt) {
        int k0 = kt * KTLE;
        const float* kbase = qkv + ((size_t)(batch * SEQ + k0)) * QKVC + DIM + head * HD;
        const float* vbase = kbase + DIM;

        __syncthreads();
        load_tile_transposed(Kst, kbase, tid);
        load_tile_direct(Vs, vbase, tid);
        __syncthreads();

        float sacc[4][4];
#pragma unroll
        for (int i = 0; i < 4; i++)
#pragma unroll
            for (int j = 0; j < 4; j++) sacc[i][j] = 0.f;

#pragma unroll 4
        for (int k = 0; k < HD; ++k) {
            float qv[4], kv[4];
#pragma unroll
            for (int i = 0; i < 4; i++) qv[i] = Qst[k * TP + srow0 + i];
#pragma unroll
            for (int j = 0; j < 4; j++) kv[j] = Kst[k * TP + scol0 + j];
#pragma unroll
            for (int i = 0; i < 4; i++)
#pragma unroll
                for (int j = 0; j < 4; j++)
                    sacc[i][j] += qv[i] * kv[j];
        }

#pragma unroll
        for (int i = 0; i < 4; i++) {
            int gi = q0 + srow0 + i;
#pragma unroll
            for (int j = 0; j < 4; j++) {
                int gj = k0 + scol0 + j;
                float v = sacc[i][j] * scale;
                Ss[(srow0 + i) * KTP + scol0 + j] = (gj > gi) ? -INFINITY : v;
            }
        }
        __syncthreads();

        if (tid < QT) {
            float mold = m_s[tid];
            float* srow = Ss + tid * KTP;
            float tm = -INFINITY;
            for (int j = 0; j < KTLE; ++j) tm = fmaxf(tm, srow[j]);
            float nm = fmaxf(mold, tm);
            float corr = __expf(mold - nm);
            float sum = 0.f;
            for (int j = 0; j < KTLE; ++j) {
                float p = __expf(srow[j] - nm);
                srow[j] = p;
                sum += p;
            }
            m_s[tid] = nm;
            l_s[tid] = l_s[tid] * corr + sum;
            cr_s[tid] = corr;
        }
        __syncthreads();

        float corr = cr_s[orow];
#pragma unroll
        for (int d = 0; d < 32; ++d) acc[d] *= corr;
        const float* prow = Ss + orow * KTP;
        for (int j = 0; j < KTLE; ++j) {
            float p = prow[j];
            const float* vp = Vs + j * HD + od0;
#pragma unroll
            for (int d = 0; d < 32; d += 4) {
                float4 v4 = *(const float4*)(vp + d);
                acc[d + 0] += p * v4.x;
                acc[d + 1] += p * v4.y;
                acc[d + 2] += p * v4.z;
                acc[d + 3] += p * v4.w;
            }
        }
    }

    float invl = 1.0f / l_s[orow];
    float* op = ctx + ((size_t)(batch * SEQ + q0 + orow)) * DIM + head * HD + od0;
#pragma unroll
    for (int d = 0; d < 32; d += 4) {
        float4 o = make_float4(acc[d] * invl, acc[d + 1] * invl,
                               acc[d + 2] * invl, acc[d + 3] * invl);
        *(float4*)(op + d) = o;
    }
}

// ---------------------------------------------------------------------------
// Launch
// ---------------------------------------------------------------------------
extern "C" void kernel_launch(void* const* d_in, const int* in_sizes, int n_in,
                              void* d_out, int out_size) {
    const float* x      = (const float*)d_in[0];
    const float* Wqkv_w = (const float*)d_in[2];
    const float* Wqkv_b = (const float*)d_in[3];
    const float* Wout_w = (const float*)d_in[4];
    const float* Wout_b = (const float*)d_in[5];
    float* out = (float*)d_out;

    void* qkv_p = nullptr;
    void* ctx_p = nullptr;
    cudaGetSymbolAddress(&qkv_p, g_qkv);
    cudaGetSymbolAddress(&ctx_p, g_ctx);
    float* qkv = (float*)qkv_p;
    float* ctx = (float*)ctx_p;

    cudaFuncSetAttribute(gemm_tf32, cudaFuncAttributeMaxDynamicSharedMemorySize,
                         GEMM_SMEM_BYTES);

    // 1) RoPE tables
    build_rope_tables<<<(SEQ * (HD / 2) + 255) / 256, 256>>>();

    // 2) QKV projection (TF32 tensor cores)
    gemm_tf32<<<dim3(QKVC / BN, NTOK / BM), 256, GEMM_SMEM_BYTES>>>(
        x, Wqkv_w, Wqkv_b, qkv, NTOK, QKVC, DIM);

    // 3) RoPE on q,k in place
    rope_kernel<<<(NTOK * 2 * NH * (HD / 2)) / 256, 256>>>();

    // 4) Flash attention
    static const size_t fa_smem = (size_t)SMEM_FLOATS * sizeof(float);
    cudaFuncSetAttribute(flash_attn, cudaFuncAttributeMaxDynamicSharedMemorySize,
                         (int)fa_smem);
    flash_attn<<<dim3(SEQ / QT, NH, BB), 256, fa_smem>>>(qkv, ctx);

    // 5) Output projection (TF32 tensor cores)
    gemm_tf32<<<dim3(DIM / BN, NTOK / BM), 256, GEMM_SMEM_BYTES>>>(
        ctx, Wout_w, Wout_b, out, NTOK, DIM, DIM);
}

// round 3
// speedup vs baseline: 3.3047x; 1.7373x over previous
#include <cuda_runtime.h>
#include <math.h>
#include <stdint.h>

// Problem constants
#define BB 4
#define SEQ 2048
#define DIM 2048
#define NH 16
#define HD 128
#define NTOK (BB * SEQ)        // 8192
#define QKVC (3 * DIM)         // 6144

// Scratch (device globals: allocation-free)
__device__ float g_qkv[(size_t)NTOK * QKVC];   // 192 MB
__device__ float g_ctx[(size_t)NTOK * DIM];    // 64 MB
__device__ float g_cos[SEQ * (HD / 2)];
__device__ float g_sin[SEQ * (HD / 2)];

// ---------------------------------------------------------------------------
// Common PTX helpers
// ---------------------------------------------------------------------------
__device__ __forceinline__ void cp_async16(float* smem, const float* gmem) {
    uint32_t s = (uint32_t)__cvta_generic_to_shared(smem);
    asm volatile("cp.async.cg.shared.global [%0], [%1], 16;\n" :: "r"(s), "l"(gmem));
}
__device__ __forceinline__ void cp_commit() {
    asm volatile("cp.async.commit_group;\n");
}
__device__ __forceinline__ void cp_wait_all() {
    asm volatile("cp.async.wait_group 0;\n");
}
__device__ __forceinline__ uint32_t f2tf32(float f) {
    uint32_t u;
    asm("cvt.rna.tf32.f32 %0, %1;\n" : "=r"(u) : "f"(f));
    return u;
}
__device__ __forceinline__ float tf32r(float f) {
    return __uint_as_float(f2tf32(f));
}
__device__ __forceinline__ void mma_tf32(float* c, const uint32_t* a, const uint32_t* b) {
    asm volatile(
        "mma.sync.aligned.m16n8k8.row.col.f32.tf32.tf32.f32 "
        "{%0,%1,%2,%3}, {%4,%5,%6,%7}, {%8,%9}, {%0,%1,%2,%3};\n"
        : "+f"(c[0]), "+f"(c[1]), "+f"(c[2]), "+f"(c[3])
        : "r"(a[0]), "r"(a[1]), "r"(a[2]), "r"(a[3]), "r"(b[0]), "r"(b[1]));
}

// ---------------------------------------------------------------------------
// RoPE tables in double precision
// ---------------------------------------------------------------------------
__global__ void build_rope_tables() {
    int idx = blockIdx.x * blockDim.x + threadIdx.x;
    if (idx >= SEQ * (HD / 2)) return;
    int pos = idx / (HD / 2);
    int i = idx % (HD / 2);
    double inv = exp(-((double)(2 * i) / (double)HD) * log(10000.0));
    double ang = (double)pos * inv;
    g_cos[idx] = (float)cos(ang);
    g_sin[idx] = (float)sin(ang);
}

__global__ void rope_kernel() {
    int idx = blockIdx.x * blockDim.x + threadIdx.x;
    const int total = NTOK * 2 * NH * (HD / 2);
    if (idx >= total) return;
    int i  = idx & 63;
    int h  = (idx >> 6) & 15;
    int qk = (idx >> 10) & 1;
    int t  = idx >> 11;
    int pos = t & (SEQ - 1);
    float c = g_cos[pos * (HD / 2) + i];
    float s = g_sin[pos * (HD / 2) + i];
    float* p = g_qkv + (size_t)t * QKVC + qk * DIM + h * HD + 2 * i;
    float x0 = p[0], x1 = p[1];
    p[0] = x0 * c - x1 * s;
    p[1] = x1 * c + x0 * s;
}

// ---------------------------------------------------------------------------
// TF32 tensor-core GEMM (unchanged from R2): C = A @ B + bias
// ---------------------------------------------------------------------------
#define BM 128
#define BN 128
#define BK 32
#define ASTRIDE 36
#define BSTRIDE 136
#define A_STAGE (BM * ASTRIDE)
#define B_STAGE (BK * BSTRIDE)
#define STAGE_FLOATS (A_STAGE + B_STAGE)
#define GEMM_SMEM_BYTES (2 * STAGE_FLOATS * 4)

__device__ __forceinline__ void load_a_stage(float* As, const float* A, int K,
                                             int brow, int ktile, int tid) {
#pragma unroll
    for (int v = 0; v < 4; v++) {
        int idx = v * 256 + tid;
        int row = idx >> 3;
        int ch = idx & 7;
        cp_async16(As + row * ASTRIDE + ch * 4,
                   A + (size_t)(brow + row) * K + ktile * BK + ch * 4);
    }
}
__device__ __forceinline__ void load_b_stage(float* Bs, const float* B, int N,
                                             int bcol, int ktile, int tid) {
#pragma unroll
    for (int v = 0; v < 4; v++) {
        int idx = v * 256 + tid;
        int row = idx >> 5;
        int ch = idx & 31;
        cp_async16(Bs + row * BSTRIDE + ch * 4,
                   B + (size_t)(ktile * BK + row) * N + bcol + ch * 4);
    }
}

__global__ __launch_bounds__(256, 2)
void gemm_tf32(const float* __restrict__ A, const float* __restrict__ B,
               const float* __restrict__ bias, float* __restrict__ C,
               int M, int N, int K) {
    extern __shared__ float sm[];
    int tid = threadIdx.x;
    int brow = blockIdx.y * BM;
    int bcol = blockIdx.x * BN;
    int warp = tid >> 5, lane = tid & 31;
    int wm = warp >> 1, wn = warp & 1;
    int g = lane >> 2, t = lane & 3;

    float c[2][8][4];
#pragma unroll
    for (int i = 0; i < 2; i++)
#pragma unroll
        for (int j = 0; j < 8; j++)
#pragma unroll
            for (int r = 0; r < 4; r++) c[i][j][r] = 0.f;

    const int NK = K / BK;

    load_a_stage(sm, A, K, brow, 0, tid);
    load_b_stage(sm + A_STAGE, B, N, bcol, 0, tid);
    cp_commit();

    int buf = 0;
    for (int kt = 0; kt < NK; kt++) {
        cp_wait_all();
        __syncthreads();
        if (kt + 1 < NK) {
            float* s2 = sm + (buf ^ 1) * STAGE_FLOATS;
            load_a_stage(s2, A, K, brow, kt + 1, tid);
            load_b_stage(s2 + A_STAGE, B, N, bcol, kt + 1, tid);
            cp_commit();
        }
        const float* As = sm + buf * STAGE_FLOATS;
        const float* Bs = As + A_STAGE;

#pragma unroll
        for (int ks = 0; ks < 4; ks++) {
            int k0 = ks * 8;
            uint32_t a[2][4], b[8][2];
#pragma unroll
            for (int mt = 0; mt < 2; mt++) {
                const float* ap = As + (wm * 32 + mt * 16 + g) * ASTRIDE + k0 + t;
                a[mt][0] = f2tf32(ap[0]);
                a[mt][1] = f2tf32(ap[8 * ASTRIDE]);
                a[mt][2] = f2tf32(ap[4]);
                a[mt][3] = f2tf32(ap[8 * ASTRIDE + 4]);
            }
#pragma unroll
            for (int nt = 0; nt < 8; nt++) {
                const float* bp = Bs + (k0 + t) * BSTRIDE + wn * 64 + nt * 8 + g;
                b[nt][0] = f2tf32(bp[0]);
                b[nt][1] = f2tf32(bp[4 * BSTRIDE]);
            }
#pragma unroll
            for (int mt = 0; mt < 2; mt++)
#pragma unroll
                for (int nt = 0; nt < 8; nt++)
                    mma_tf32(c[mt][nt], a[mt], b[nt]);
        }
        buf ^= 1;
    }

#pragma unroll
    for (int mt = 0; mt < 2; mt++) {
        int r0 = brow + wm * 32 + mt * 16 + g;
#pragma unroll
        for (int nt = 0; nt < 8; nt++) {
            int col = bcol + wn * 64 + nt * 8 + 2 * t;
            float b0 = bias[col], b1 = bias[col + 1];
            float2 v0 = make_float2(c[mt][nt][0] + b0, c[mt][nt][1] + b1);
            float2 v1 = make_float2(c[mt][nt][2] + b0, c[mt][nt][3] + b1);
            *(float2*)(C + (size_t)r0 * N + col) = v0;
            *(float2*)(C + (size_t)(r0 + 8) * N + col) = v1;
        }
    }
}

// ---------------------------------------------------------------------------
// Tensor-core flash attention (TF32 mma, fp32 softmax, causal).
// CTA: 128 q-rows x 1 head. 8 warps, each owns 16 q-rows. K/V tiles of 64.
// S = Q@K^T directly; O computed transposed (O^T = V^T @ P^T) so V needs
// no smem transpose and all fragment LDS are bank-conflict-free.
// ---------------------------------------------------------------------------
#define FQT 128
#define FKT 64
#define QPAD 132
#define KPAD 132
#define VPAD 132
#define SPAD 76
#define FA_SMEM_FLOATS (FQT * QPAD + FKT * KPAD + FKT * VPAD + FQT * SPAD + 256)
#define FA_SMEM_BYTES (FA_SMEM_FLOATS * 4)

__device__ __forceinline__ uint32_t fu(float f) { return __float_as_uint(f); }

__global__ __launch_bounds__(256, 1)
void flash_attn_mma(const float* __restrict__ qkv, float* __restrict__ ctx) {
    int qtile = blockIdx.x, head = blockIdx.y, batch = blockIdx.z;
    int q0 = qtile * FQT;
    int tid = threadIdx.x, warp = tid >> 5, lane = tid & 31;
    int g = lane >> 2, t = lane & 3;

    extern __shared__ float sm[];
    float* Qs = sm;                       // [128][132]
    float* Ks = Qs + FQT * QPAD;          // [64][132]
    float* Vs = Ks + FKT * KPAD;          // [64][132]
    float* Ss = Vs + FKT * VPAD;          // [128][76]   P tile (warp-private rows)
    float* cr = Ss + FQT * SPAD;          // [128] per-row corr
    float* ls = cr + 128;                 // [128] per-row l

    const float scale = 0.08838834764831845f;  // 1/sqrt(128)
    const float* qbase = qkv + (size_t)(batch * SEQ + q0) * QKVC + head * HD;

    // Load Q once: fold scale, round to tf32
#pragma unroll
    for (int v = 0; v < 16; v++) {
        int idx = v * 256 + tid;
        int row = idx >> 5, ch = (idx & 31) << 2;
        float4 x = *(const float4*)(qbase + (size_t)row * QKVC + ch);
        float* d = Qs + row * QPAD + ch;
        d[0] = tf32r(x.x * scale);
        d[1] = tf32r(x.y * scale);
        d[2] = tf32r(x.z * scale);
        d[3] = tf32r(x.w * scale);
    }

    // O^T accumulators: o[mt(8 d-tiles)][nt(2 q-tiles)][4]
    float o[8][2][4];
#pragma unroll
    for (int mt = 0; mt < 8; mt++)
#pragma unroll
        for (int nt = 0; nt < 2; nt++)
#pragma unroll
            for (int r = 0; r < 4; r++) o[mt][nt][r] = 0.f;

    float m_a = -INFINITY, m_b = -INFINITY, l_a = 0.f, l_b = 0.f;
    int rowa = q0 + warp * 16 + g;
    int rowb = rowa + 8;
    int ntiles = 2 * (qtile + 1);

    for (int kt = 0; kt < ntiles; kt++) {
        int k0g = kt * FKT;
        const float* kbase = qkv + (size_t)(batch * SEQ + k0g) * QKVC + DIM + head * HD;
        const float* vbase = kbase + DIM;

        __syncthreads();
#pragma unroll
        for (int v = 0; v < 8; v++) {
            int idx = v * 256 + tid;
            int row = idx >> 5, ch = (idx & 31) << 2;
            float4 kx = *(const float4*)(kbase + (size_t)row * QKVC + ch);
            float4 vx = *(const float4*)(vbase + (size_t)row * QKVC + ch);
            float* kd = Ks + row * KPAD + ch;
            kd[0] = tf32r(kx.x); kd[1] = tf32r(kx.y);
            kd[2] = tf32r(kx.z); kd[3] = tf32r(kx.w);
            float* vd = Vs + row * VPAD + ch;
            vd[0] = tf32r(vx.x); vd[1] = tf32r(vx.y);
            vd[2] = tf32r(vx.z); vd[3] = tf32r(vx.w);
        }
        __syncthreads();

        // ---- S = Q @ K^T  (per warp: 16 rows x 64 kv) ----
        float sc[8][4];
#pragma unroll
        for (int nt = 0; nt < 8; nt++)
#pragma unroll
            for (int r = 0; r < 4; r++) sc[nt][r] = 0.f;

#pragma unroll
        for (int k8 = 0; k8 < HD; k8 += 8) {
            uint32_t a[4];
            const float* qp = Qs + (warp * 16 + g) * QPAD + k8 + t;
            a[0] = fu(qp[0]);
            a[1] = fu(qp[8 * QPAD]);
            a[2] = fu(qp[4]);
            a[3] = fu(qp[8 * QPAD + 4]);
#pragma unroll
            for (int nt = 0; nt < 8; nt++) {
                uint32_t b[2];
                const float* kp = Ks + (nt * 8 + g) * KPAD + k8 + t;
                b[0] = fu(kp[0]);
                b[1] = fu(kp[4]);
                mma_tf32(sc[nt], a, b);
            }
        }

        // ---- causal mask (only the two diagonal tiles need it) ----
        if (kt >= 2 * qtile) {
#pragma unroll
            for (int nt = 0; nt < 8; nt++) {
                int col = k0g + nt * 8 + 2 * t;
                if (col > rowa) sc[nt][0] = -INFINITY;
                if (col + 1 > rowa) sc[nt][1] = -INFINITY;
                if (col > rowb) sc[nt][2] = -INFINITY;
                if (col + 1 > rowb) sc[nt][3] = -INFINITY;
            }
        }

        // ---- online softmax (quad = lanes sharing g) ----
        float tma = -INFINITY, tmb = -INFINITY;
#pragma unroll
        for (int nt = 0; nt < 8; nt++) {
            tma = fmaxf(tma, fmaxf(sc[nt][0], sc[nt][1]));
            tmb = fmaxf(tmb, fmaxf(sc[nt][2], sc[nt][3]));
        }
        tma = fmaxf(tma, __shfl_xor_sync(0xffffffff, tma, 1));
        tma = fmaxf(tma, __shfl_xor_sync(0xffffffff, tma, 2));
        tmb = fmaxf(tmb, __shfl_xor_sync(0xffffffff, tmb, 1));
        tmb = fmaxf(tmb, __shfl_xor_sync(0xffffffff, tmb, 2));

        float nma = fmaxf(m_a, tma), nmb = fmaxf(m_b, tmb);
        float ca = __expf(m_a - nma), cb = __expf(m_b - nmb);
        m_a = nma; m_b = nmb;

        float sa = 0.f, sb = 0.f;
#pragma unroll
        for (int nt = 0; nt < 8; nt++) {
            float p0 = __expf(sc[nt][0] - nma);
            float p1 = __expf(sc[nt][1] - nma);
            float p2 = __expf(sc[nt][2] - nmb);
            float p3 = __expf(sc[nt][3] - nmb);
            sc[nt][0] = p0; sc[nt][1] = p1; sc[nt][2] = p2; sc[nt][3] = p3;
            sa += p0 + p1;
            sb += p2 + p3;
        }
        sa += __shfl_xor_sync(0xffffffff, sa, 1);
        sa += __shfl_xor_sync(0xffffffff, sa, 2);
        sb += __shfl_xor_sync(0xffffffff, sb, 1);
        sb += __shfl_xor_sync(0xffffffff, sb, 2);
        l_a = l_a * ca + sa;
        l_b = l_b * cb + sb;

        if (t == 0) {
            cr[warp * 16 + g] = ca;
            cr[warp * 16 + g + 8] = cb;
        }

        // ---- write P to smem (warp-private rows) ----
#pragma unroll
        for (int nt = 0; nt < 8; nt++) {
            *(float2*)(Ss + (warp * 16 + g) * SPAD + nt * 8 + 2 * t) =
                make_float2(sc[nt][0], sc[nt][1]);
            *(float2*)(Ss + (warp * 16 + g + 8) * SPAD + nt * 8 + 2 * t) =
                make_float2(sc[nt][2], sc[nt][3]);
        }
        __syncwarp();

        // ---- rescale O^T by per-row corr ----
#pragma unroll
        for (int nt = 0; nt < 2; nt++) {
            float c0 = cr[warp * 16 + nt * 8 + 2 * t];
            float c1 = cr[warp * 16 + nt * 8 + 2 * t + 1];
#pragma unroll
            for (int mt = 0; mt < 8; mt++) {
                o[mt][nt][0] *= c0;
                o[mt][nt][1] *= c1;
                o[mt][nt][2] *= c0;
                o[mt][nt][3] *= c1;
            }
        }

        // ---- O^T += V^T @ P^T ----
#pragma unroll
        for (int k8 = 0; k8 < FKT; k8 += 8) {
            uint32_t b[2][2];
#pragma unroll
            for (int nt = 0; nt < 2; nt++) {
                const float* pp = Ss + (warp * 16 + nt * 8 + g) * SPAD + k8 + t;
                b[nt][0] = f2tf32(pp[0]);
                b[nt][1] = f2tf32(pp[4]);
            }
#pragma unroll
            for (int mt = 0; mt < 8; mt++) {
                uint32_t a[4];
                const float* vp = Vs + (k8 + t) * VPAD + mt * 16 + g;
                a[0] = fu(vp[0]);
                a[1] = fu(vp[8]);
                a[2] = fu(vp[4 * VPAD]);
                a[3] = fu(vp[4 * VPAD + 8]);
                mma_tf32(o[mt][0], a, b[0]);
                mma_tf32(o[mt][1], a, b[1]);
            }
        }
    }

    // ---- epilogue: O = O^T / l ----
    if (t == 0) {
        ls[warp * 16 + g] = l_a;
        ls[warp * 16 + g + 8] = l_b;
    }
    __syncwarp();

#pragma unroll
    for (int nt = 0; nt < 2; nt++) {
        int q_loc = warp * 16 + nt * 8 + 2 * t;
        float il0 = 1.0f / ls[q_loc];
        float il1 = 1.0f / ls[q_loc + 1];
        size_t r0 = (size_t)(batch * SEQ + q0 + q_loc) * DIM + head * HD;
        size_t r1 = r0 + DIM;
#pragma unroll
        for (int mt = 0; mt < 8; mt++) {
            int d = mt * 16 + g;
            ctx[r0 + d] = o[mt][nt][0] * il0;
            ctx[r1 + d] = o[mt][nt][1] * il1;
            ctx[r0 + d + 8] = o[mt][nt][2] * il0;
            ctx[r1 + d + 8] = o[mt][nt][3] * il1;
        }
    }
}

// ---------------------------------------------------------------------------
// Launch
// ---------------------------------------------------------------------------
extern "C" void kernel_launch(void* const* d_in, const int* in_sizes, int n_in,
                              void* d_out, int out_size) {
    const float* x      = (const float*)d_in[0];
    const float* Wqkv_w = (const float*)d_in[2];
    const float* Wqkv_b = (const float*)d_in[3];
    const float* Wout_w = (const float*)d_in[4];
    const float* Wout_b = (const float*)d_in[5];
    float* out = (float*)d_out;

    void* qkv_p = nullptr;
    void* ctx_p = nullptr;
    cudaGetSymbolAddress(&qkv_p, g_qkv);
    cudaGetSymbolAddress(&ctx_p, g_ctx);
    float* qkv = (float*)qkv_p;
    float* ctx = (float*)ctx_p;

    cudaFuncSetAttribute(gemm_tf32, cudaFuncAttributeMaxDynamicSharedMemorySize,
                         GEMM_SMEM_BYTES);
    cudaFuncSetAttribute(flash_attn_mma,
                         cudaFuncAttributeMaxDynamicSharedMemorySize, FA_SMEM_BYTES);

    // 1) RoPE tables
    build_rope_tables<<<(SEQ * (HD / 2) + 255) / 256, 256>>>();

    // 2) QKV projection (TF32 tensor cores)
    gemm_tf32<<<dim3(QKVC / BN, NTOK / BM), 256, GEMM_SMEM_BYTES>>>(
        x, Wqkv_w, Wqkv_b, qkv, NTOK, QKVC, DIM);

    // 3) RoPE on q,k in place
    rope_kernel<<<(NTOK * 2 * NH * (HD / 2)) / 256, 256>>>();

    // 4) Flash attention (TF32 tensor cores)
    flash_attn_mma<<<dim3(SEQ / FQT, NH, BB), 256, FA_SMEM_BYTES>>>(qkv, ctx);

    // 5) Output projection (TF32 tensor cores)
    gemm_tf32<<<dim3(DIM / BN, NTOK / BM), 256, GEMM_SMEM_BYTES>>>(
        ctx, Wout_w, Wout_b, out, NTOK, DIM, DIM);
}

// round 4
// speedup vs baseline: 3.5868x; 1.0854x over previous
#include <cuda_runtime.h>
#include <math.h>
#include <stdint.h>

// Problem constants
#define BB 4
#define SEQ 2048
#define DIM 2048
#define NH 16
#define HD 128
#define NTOK (BB * SEQ)        // 8192
#define QKVC (3 * DIM)         // 6144

// Scratch (device globals: allocation-free)
__device__ float g_qkv[(size_t)NTOK * QKVC];   // 192 MB
__device__ float g_ctx[(size_t)NTOK * DIM];    // 64 MB
__device__ float g_xr[(size_t)NTOK * DIM];     // 67 MB  tf32-rounded x
__device__ float g_w1[(size_t)DIM * QKVC];     // 50 MB  tf32-rounded Wqkv
__device__ float g_w2[(size_t)DIM * DIM];      // 17 MB  tf32-rounded Wout
__device__ float g_cos[SEQ * (HD / 2)];
__device__ float g_sin[SEQ * (HD / 2)];

// ---------------------------------------------------------------------------
// PTX helpers
// ---------------------------------------------------------------------------
__device__ __forceinline__ void cp_async16(float* smem, const float* gmem) {
    uint32_t s = (uint32_t)__cvta_generic_to_shared(smem);
    asm volatile("cp.async.cg.shared.global [%0], [%1], 16;\n" :: "r"(s), "l"(gmem));
}
__device__ __forceinline__ void cp_commit() {
    asm volatile("cp.async.commit_group;\n");
}
__device__ __forceinline__ void cp_wait0() {
    asm volatile("cp.async.wait_group 0;\n");
}
__device__ __forceinline__ void cp_wait1() {
    asm volatile("cp.async.wait_group 1;\n");
}
__device__ __forceinline__ uint32_t f2tf32(float f) {
    uint32_t u;
    asm("cvt.rna.tf32.f32 %0, %1;\n" : "=r"(u) : "f"(f));
    return u;
}
__device__ __forceinline__ float tf32r(float f) {
    return __uint_as_float(f2tf32(f));
}
__device__ __forceinline__ uint32_t fu(float f) { return __float_as_uint(f); }

__device__ __forceinline__ void mma_tf32(float* c, const uint32_t* a, const uint32_t* b) {
    asm volatile(
        "mma.sync.aligned.m16n8k8.row.col.f32.tf32.tf32.f32 "
        "{%0,%1,%2,%3}, {%4,%5,%6,%7}, {%8,%9}, {%0,%1,%2,%3};\n"
        : "+f"(c[0]), "+f"(c[1]), "+f"(c[2]), "+f"(c[3])
        : "r"(a[0]), "r"(a[1]), "r"(a[2]), "r"(a[3]), "r"(b[0]), "r"(b[1]));
}

// ---------------------------------------------------------------------------
// Elementwise tf32 rounding (vectorized)
// ---------------------------------------------------------------------------
__global__ void round_tf32(const float* __restrict__ src, float* __restrict__ dst,
                           int n4) {
    int i = blockIdx.x * blockDim.x + threadIdx.x;
    if (i >= n4) return;
    float4 v = ((const float4*)src)[i];
    v.x = tf32r(v.x); v.y = tf32r(v.y); v.z = tf32r(v.z); v.w = tf32r(v.w);
    ((float4*)dst)[i] = v;
}

// ---------------------------------------------------------------------------
// RoPE tables in double precision
// ---------------------------------------------------------------------------
__global__ void build_rope_tables() {
    int idx = blockIdx.x * blockDim.x + threadIdx.x;
    if (idx >= SEQ * (HD / 2)) return;
    int pos = idx / (HD / 2);
    int i = idx % (HD / 2);
    double inv = exp(-((double)(2 * i) / (double)HD) * log(10000.0));
    double ang = (double)pos * inv;
    g_cos[idx] = (float)cos(ang);
    g_sin[idx] = (float)sin(ang);
}

// RoPE on q,k in place; outputs tf32-rounded so flash can use raw bits.
__global__ void rope_kernel() {
    int idx = blockIdx.x * blockDim.x + threadIdx.x;
    const int total = NTOK * 2 * NH * (HD / 2);
    if (idx >= total) return;
    int i  = idx & 63;
    int h  = (idx >> 6) & 15;
    int qk = (idx >> 10) & 1;
    int t  = idx >> 11;
    int pos = t & (SEQ - 1);
    float c = g_cos[pos * (HD / 2) + i];
    float s = g_sin[pos * (HD / 2) + i];
    float* p = g_qkv + (size_t)t * QKVC + qk * DIM + h * HD + 2 * i;
    float x0 = p[0], x1 = p[1];
    p[0] = tf32r(x0 * c - x1 * s);
    p[1] = tf32r(x1 * c + x0 * s);
}

// ---------------------------------------------------------------------------
// TF32 tensor-core GEMM: C = A @ B + bias. Inputs pre-rounded to tf32.
// rnd_out: round C to tf32 (for tensors feeding later MMAs).
// ---------------------------------------------------------------------------
#define BM 128
#define BN 128
#define BK 32
#define ASTRIDE 36
#define BSTRIDE 136
#define A_STAGE (BM * ASTRIDE)
#define B_STAGE (BK * BSTRIDE)
#define STAGE_FLOATS (A_STAGE + B_STAGE)
#define GEMM_SMEM_BYTES (2 * STAGE_FLOATS * 4)

__device__ __forceinline__ void load_a_stage(float* As, const float* A, int K,
                                             int brow, int ktile, int tid) {
#pragma unroll
    for (int v = 0; v < 4; v++) {
        int idx = v * 256 + tid;
        int row = idx >> 3;
        int ch = idx & 7;
        cp_async16(As + row * ASTRIDE + ch * 4,
                   A + (size_t)(brow + row) * K + ktile * BK + ch * 4);
    }
}
__device__ __forceinline__ void load_b_stage(float* Bs, const float* B, int N,
                                             int bcol, int ktile, int tid) {
#pragma unroll
    for (int v = 0; v < 4; v++) {
        int idx = v * 256 + tid;
        int row = idx >> 5;
        int ch = idx & 31;
        cp_async16(Bs + row * BSTRIDE + ch * 4,
                   B + (size_t)(ktile * BK + row) * N + bcol + ch * 4);
    }
}

__global__ __launch_bounds__(256, 2)
void gemm_tf32(const float* __restrict__ A, const float* __restrict__ B,
               const float* __restrict__ bias, float* __restrict__ C,
               int M, int N, int K, int rnd_out) {
    extern __shared__ float sm[];
    int tid = threadIdx.x;
    int brow = blockIdx.y * BM;
    int bcol = blockIdx.x * BN;
    int warp = tid >> 5, lane = tid & 31;
    int wm = warp >> 1, wn = warp & 1;
    int g = lane >> 2, t = lane & 3;

    float c[2][8][4];
#pragma unroll
    for (int i = 0; i < 2; i++)
#pragma unroll
        for (int j = 0; j < 8; j++)
#pragma unroll
            for (int r = 0; r < 4; r++) c[i][j][r] = 0.f;

    const int NK = K / BK;

    load_a_stage(sm, A, K, brow, 0, tid);
    load_b_stage(sm + A_STAGE, B, N, bcol, 0, tid);
    cp_commit();

    int buf = 0;
    for (int kt = 0; kt < NK; kt++) {
        cp_wait0();
        __syncthreads();
        if (kt + 1 < NK) {
            float* s2 = sm + (buf ^ 1) * STAGE_FLOATS;
            load_a_stage(s2, A, K, brow, kt + 1, tid);
            load_b_stage(s2 + A_STAGE, B, N, bcol, kt + 1, tid);
            cp_commit();
        }
        const float* As = sm + buf * STAGE_FLOATS;
        const float* Bs = As + A_STAGE;

#pragma unroll
        for (int ks = 0; ks < 4; ks++) {
            int k0 = ks * 8;
            uint32_t a[2][4], b[8][2];
#pragma unroll
            for (int mt = 0; mt < 2; mt++) {
                const float* ap = As + (wm * 32 + mt * 16 + g) * ASTRIDE + k0 + t;
                a[mt][0] = fu(ap[0]);
                a[mt][1] = fu(ap[8 * ASTRIDE]);
                a[mt][2] = fu(ap[4]);
                a[mt][3] = fu(ap[8 * ASTRIDE + 4]);
            }
#pragma unroll
            for (int nt = 0; nt < 8; nt++) {
                const float* bp = Bs + (k0 + t) * BSTRIDE + wn * 64 + nt * 8 + g;
                b[nt][0] = fu(bp[0]);
                b[nt][1] = fu(bp[4 * BSTRIDE]);
            }
#pragma unroll
            for (int mt = 0; mt < 2; mt++)
#pragma unroll
                for (int nt = 0; nt < 8; nt++)
                    mma_tf32(c[mt][nt], a[mt], b[nt]);
        }
        buf ^= 1;
    }

#pragma unroll
    for (int mt = 0; mt < 2; mt++) {
        int r0 = brow + wm * 32 + mt * 16 + g;
#pragma unroll
        for (int nt = 0; nt < 8; nt++) {
            int col = bcol + wn * 64 + nt * 8 + 2 * t;
            float b0 = bias[col], b1 = bias[col + 1];
            float v00 = c[mt][nt][0] + b0, v01 = c[mt][nt][1] + b1;
            float v10 = c[mt][nt][2] + b0, v11 = c[mt][nt][3] + b1;
            if (rnd_out) {
                v00 = tf32r(v00); v01 = tf32r(v01);
                v10 = tf32r(v10); v11 = tf32r(v11);
            }
            *(float2*)(C + (size_t)r0 * N + col) = make_float2(v00, v01);
            *(float2*)(C + (size_t)(r0 + 8) * N + col) = make_float2(v10, v11);
        }
    }
}

// ---------------------------------------------------------------------------
// Tensor-core flash attention (TF32 mma, fp32 softmax, causal).
// CTA: 128 q-rows x 1 head, 8 warps. K/V tiles of 64 rows.
// Inputs pre-rounded to tf32 (RoPE/epilogue) -> raw-bit fragment loads.
// cp.async pipeline: K double-buffered, V issued one iteration early.
// O computed transposed (O^T = V^T @ P^T).
// ---------------------------------------------------------------------------
#define FQT 128
#define FKT 64
#define QPAD 132
#define KPAD 132
#define VPAD 132
#define SPAD 76
#define KSTG (FKT * KPAD)
#define FA_SMEM_FLOATS (FQT * QPAD + 2 * KSTG + FKT * VPAD + FQT * SPAD + 256)
#define FA_SMEM_BYTES (FA_SMEM_FLOATS * 4)

__device__ __forceinline__ void fa_load_tile_async(float* dst, const float* gsrc,
                                                   int tid) {
#pragma unroll
    for (int v = 0; v < 8; v++) {
        int idx = v * 256 + tid;
        int row = idx >> 5, ch = (idx & 31) << 2;
        cp_async16(dst + row * KPAD + ch, gsrc + (size_t)row * QKVC + ch);
    }
}

__global__ __launch_bounds__(256, 1)
void flash_attn_mma(const float* __restrict__ qkv, float* __restrict__ ctx) {
    int qtile = blockIdx.x, head = blockIdx.y, batch = blockIdx.z;
    int q0 = qtile * FQT;
    int tid = threadIdx.x, warp = tid >> 5, lane = tid & 31;
    int g = lane >> 2, t = lane & 3;

    extern __shared__ float sm[];
    float* Qs = sm;                         // [128][132]
    float* Ks0 = Qs + FQT * QPAD;           // [2][64][132]
    float* Vs = Ks0 + 2 * KSTG;             // [64][132]
    float* Ss = Vs + FKT * VPAD;            // [128][76]
    float* cr = Ss + FQT * SPAD;            // [128]
    float* ls = cr + 128;                   // [128]

    const float scale = 0.08838834764831845f;  // 1/sqrt(128)
    const float* qbase = qkv + (size_t)(batch * SEQ + q0) * QKVC + head * HD;
    const float* kvbase = qkv + (size_t)(batch * SEQ) * QKVC + DIM + head * HD;

    int ntiles = 2 * (qtile + 1);

    // Prologue: issue K[0] then V[0]
    fa_load_tile_async(Ks0, kvbase, tid);
    cp_commit();
    fa_load_tile_async(Vs, kvbase + DIM, tid);
    cp_commit();

    // Q load (plain; raw tf32 bits)
#pragma unroll
    for (int v = 0; v < 16; v++) {
        int idx = v * 256 + tid;
        int row = idx >> 5, ch = (idx & 31) << 2;
        *(float4*)(Qs + row * QPAD + ch) =
            *(const float4*)(qbase + (size_t)row * QKVC + ch);
    }

    float o[8][2][4];
#pragma unroll
    for (int mt = 0; mt < 8; mt++)
#pragma unroll
        for (int nt = 0; nt < 2; nt++)
#pragma unroll
            for (int r = 0; r < 4; r++) o[mt][nt][r] = 0.f;

    float m_a = -INFINITY, m_b = -INFINITY, l_a = 0.f, l_b = 0.f;
    int rowa = q0 + warp * 16 + g;
    int rowb = rowa + 8;

    int buf = 0;
    for (int kt = 0; kt < ntiles; kt++) {
        int k0g = kt * FKT;
        const float* kvtile = kvbase + (size_t)k0g * QKVC;

        // K[kt] ready (leave V[kt] pending)
        cp_wait1();
        __syncthreads();
        if (kt + 1 < ntiles) {
            fa_load_tile_async(Ks0 + (buf ^ 1) * KSTG,
                               kvtile + (size_t)FKT * QKVC, tid);
            cp_commit();
        }
        const float* Ks = Ks0 + buf * KSTG;

        // ---- S = Q @ K^T ----
        float sc[8][4];
#pragma unroll
        for (int nt = 0; nt < 8; nt++)
#pragma unroll
            for (int r = 0; r < 4; r++) sc[nt][r] = 0.f;

#pragma unroll
        for (int k8 = 0; k8 < HD; k8 += 8) {
            uint32_t a[4];
            const float* qp = Qs + (warp * 16 + g) * QPAD + k8 + t;
            a[0] = fu(qp[0]);
            a[1] = fu(qp[8 * QPAD]);
            a[2] = fu(qp[4]);
            a[3] = fu(qp[8 * QPAD + 4]);
#pragma unroll
            for (int nt = 0; nt < 8; nt++) {
                uint32_t b[2];
                const float* kp = Ks + (nt * 8 + g) * KPAD + k8 + t;
                b[0] = fu(kp[0]);
                b[1] = fu(kp[4]);
                mma_tf32(sc[nt], a, b);
            }
        }

        // ---- scale + causal mask ----
#pragma unroll
        for (int nt = 0; nt < 8; nt++)
#pragma unroll
            for (int r = 0; r < 4; r++) sc[nt][r] *= scale;

        if (kt >= 2 * qtile) {
#pragma unroll
            for (int nt = 0; nt < 8; nt++) {
                int col = k0g + nt * 8 + 2 * t;
                if (col > rowa) sc[nt][0] = -INFINITY;
                if (col + 1 > rowa) sc[nt][1] = -INFINITY;
                if (col > rowb) sc[nt][2] = -INFINITY;
                if (col + 1 > rowb) sc[nt][3] = -INFINITY;
            }
        }

        // ---- online softmax (quad reductions) ----
        float tma = -INFINITY, tmb = -INFINITY;
#pragma unroll
        for (int nt = 0; nt < 8; nt++) {
            tma = fmaxf(tma, fmaxf(sc[nt][0], sc[nt][1]));
            tmb = fmaxf(tmb, fmaxf(sc[nt][2], sc[nt][3]));
        }
        tma = fmaxf(tma, __shfl_xor_sync(0xffffffff, tma, 1));
        tma = fmaxf(tma, __shfl_xor_sync(0xffffffff, tma, 2));
        tmb = fmaxf(tmb, __shfl_xor_sync(0xffffffff, tmb, 1));
        tmb = fmaxf(tmb, __shfl_xor_sync(0xffffffff, tmb, 2));

        float nma = fmaxf(m_a, tma), nmb = fmaxf(m_b, tmb);
        float ca = __expf(m_a - nma), cb = __expf(m_b - nmb);
        m_a = nma; m_b = nmb;

        float sa = 0.f, sb = 0.f;
#pragma unroll
        for (int nt = 0; nt < 8; nt++) {
            float p0 = __expf(sc[nt][0] - nma);
            float p1 = __expf(sc[nt][1] - nma);
            float p2 = __expf(sc[nt][2] - nmb);
            float p3 = __expf(sc[nt][3] - nmb);
            sc[nt][0] = p0; sc[nt][1] = p1; sc[nt][2] = p2; sc[nt][3] = p3;
            sa += p0 + p1;
            sb += p2 + p3;
        }
        sa += __shfl_xor_sync(0xffffffff, sa, 1);
        sa += __shfl_xor_sync(0xffffffff, sa, 2);
        sb += __shfl_xor_sync(0xffffffff, sb, 1);
        sb += __shfl_xor_sync(0xffffffff, sb, 2);
        l_a = l_a * ca + sa;
        l_b = l_b * cb + sb;

        if (t == 0) {
            cr[warp * 16 + g] = ca;
            cr[warp * 16 + g + 8] = cb;
        }

        // ---- write P (warp-private rows) ----
#pragma unroll
        for (int nt = 0; nt < 8; nt++) {
            *(float2*)(Ss + (warp * 16 + g) * SPAD + nt * 8 + 2 * t) =
                make_float2(sc[nt][0], sc[nt][1]);
            *(float2*)(Ss + (warp * 16 + g + 8) * SPAD + nt * 8 + 2 * t) =
                make_float2(sc[nt][2], sc[nt][3]);
        }

        // V[kt] ready
        if (kt + 1 < ntiles) cp_wait1(); else cp_wait0();
        __syncthreads();

        // ---- rescale O^T ----
#pragma unroll
        for (int nt = 0; nt < 2; nt++) {
            float c0 = cr[warp * 16 + nt * 8 + 2 * t];
            float c1 = cr[warp * 16 + nt * 8 + 2 * t + 1];
#pragma unroll
            for (int mt = 0; mt < 8; mt++) {
                o[mt][nt][0] *= c0;
                o[mt][nt][1] *= c1;
                o[mt][nt][2] *= c0;
                o[mt][nt][3] *= c1;
            }
        }

        // ---- O^T += V^T @ P^T ----
#pragma unroll
        for (int k8 = 0; k8 < FKT; k8 += 8) {
            uint32_t b[2][2];
#pragma unroll
            for (int nt = 0; nt < 2; nt++) {
                const float* pp = Ss + (warp * 16 + nt * 8 + g) * SPAD + k8 + t;
                b[nt][0] = f2tf32(pp[0]);
                b[nt][1] = f2tf32(pp[4]);
            }
#pragma unroll
            for (int mt = 0; mt < 8; mt++) {
                uint32_t a[4];
                const float* vp = Vs + (k8 + t) * VPAD + mt * 16 + g;
                a[0] = fu(vp[0]);
                a[1] = fu(vp[8]);
                a[2] = fu(vp[4 * VPAD]);
                a[3] = fu(vp[4 * VPAD + 8]);
                mma_tf32(o[mt][0], a, b[0]);
                mma_tf32(o[mt][1], a, b[1]);
            }
        }

        // all reads of Vs done; issue V[kt+1]
        __syncthreads();
        if (kt + 1 < ntiles) {
            fa_load_tile_async(Vs, kvtile + (size_t)FKT * QKVC + DIM, tid);
            cp_commit();
        }
        buf ^= 1;
    }

    // ---- epilogue: O = O^T / l, rounded to tf32 for the out-projection ----
    if (t == 0) {
        ls[warp * 16 + g] = l_a;
        ls[warp * 16 + g + 8] = l_b;
    }
    __syncwarp();

#pragma unroll
    for (int nt = 0; nt < 2; nt++) {
        int q_loc = warp * 16 + nt * 8 + 2 * t;
        float il0 = 1.0f / ls[q_loc];
        float il1 = 1.0f / ls[q_loc + 1];
        size_t r0 = (size_t)(batch * SEQ + q0 + q_loc) * DIM + head * HD;
        size_t r1 = r0 + DIM;
#pragma unroll
        for (int mt = 0; mt < 8; mt++) {
            int d = mt * 16 + g;
            ctx[r0 + d] = tf32r(o[mt][nt][0] * il0);
            ctx[r1 + d] = tf32r(o[mt][nt][1] * il1);
            ctx[r0 + d + 8] = tf32r(o[mt][nt][2] * il0);
            ctx[r1 + d + 8] = tf32r(o[mt][nt][3] * il1);
        }
    }
}

// ---------------------------------------------------------------------------
// Launch
// ---------------------------------------------------------------------------
extern "C" void kernel_launch(void* const* d_in, const int* in_sizes, int n_in,
                              void* d_out, int out_size) {
    const float* x      = (const float*)d_in[0];
    const float* Wqkv_w = (const float*)d_in[2];
    const float* Wqkv_b = (const float*)d_in[3];
    const float* Wout_w = (const float*)d_in[4];
    const float* Wout_b = (const float*)d_in[5];
    float* out = (float*)d_out;

    void *qkv_p, *ctx_p, *xr_p, *w1_p, *w2_p;
    cudaGetSymbolAddress(&qkv_p, g_qkv);
    cudaGetSymbolAddress(&ctx_p, g_ctx);
    cudaGetSymbolAddress(&xr_p, g_xr);
    cudaGetSymbolAddress(&w1_p, g_w1);
    cudaGetSymbolAddress(&w2_p, g_w2);
    float* qkv = (float*)qkv_p;
    float* ctx = (float*)ctx_p;
    float* xr  = (float*)xr_p;
    float* w1  = (float*)w1_p;
    float* w2  = (float*)w2_p;

    cudaFuncSetAttribute(gemm_tf32, cudaFuncAttributeMaxDynamicSharedMemorySize,
                         GEMM_SMEM_BYTES);
    cudaFuncSetAttribute(flash_attn_mma,
                         cudaFuncAttributeMaxDynamicSharedMemorySize, FA_SMEM_BYTES);

    // 0) Pre-round operands to tf32
    round_tf32<<<(NTOK * DIM / 4 + 255) / 256, 256>>>(x, xr, NTOK * DIM / 4);
    round_tf32<<<(DIM * QKVC / 4 + 255) / 256, 256>>>(Wqkv_w, w1, DIM * QKVC / 4);
    round_tf32<<<(DIM * DIM / 4 + 255) / 256, 256>>>(Wout_w, w2, DIM * DIM / 4);

    // 1) RoPE tables
    build_rope_tables<<<(SEQ * (HD / 2) + 255) / 256, 256>>>();

    // 2) QKV projection (rounded output feeds attention MMAs)
    gemm_tf32<<<dim3(QKVC / BN, NTOK / BM), 256, GEMM_SMEM_BYTES>>>(
        xr, w1, Wqkv_b, qkv, NTOK, QKVC, DIM, 1);

    // 3) RoPE on q,k in place (rounded output)
    rope_kernel<<<(NTOK * 2 * NH * (HD / 2)) / 256, 256>>>();

    // 4) Flash attention (ctx rounded in epilogue)
    flash_attn_mma<<<dim3(SEQ / FQT, NH, BB), 256, FA_SMEM_BYTES>>>(qkv, ctx);

    // 5) Output projection (fp32 output)
    gemm_tf32<<<dim3(DIM / BN, NTOK / BM), 256, GEMM_SMEM_BYTES>>>(
        ctx, w2, Wout_b, out, NTOK, DIM, DIM, 0);
}